// round 16
// baseline (speedup 1.0000x reference)
#include <cuda_runtime.h>
#include <cuda_fp16.h>
#include <cstdint>

#define NROWS 262144
#define HC 64
#define KOFF 27
#define TILE_M 128
#define NBLK (NROWS / TILE_M)
#define NSTAGE 3

// weight fragments per layer: 27 k * 4 ks * 8 nt * 32 lanes uint2 (fp16)
#define WFRAG_PER_LAYER (KOFF * 4 * 8 * 32)

// ---------------- device scratch (no allocations allowed) ----------------
// Row NROWS is a zero sentinel (zero-initialized, never written) so gathers
// need no bounds check.
__device__ __align__(128) __half g_xf[(size_t)(NROWS + 8) * HC];  // fp16 x
__device__ __align__(128) __half g_mf[(size_t)(NROWS + 8) * HC];  // fp16 mid
// W in mma-B fragment order: uint2 = {b_r0, b_r1}
__device__ uint2 g_wf[2 * WFRAG_PER_LAYER];

// ---------------- helpers (baseline PTX: ldmatrix / mma.sync / bar) ------
__device__ __forceinline__ uint32_t smem_u32(const void* p) {
    uint32_t a;
    asm("{ .reg .u64 t; cvta.to.shared.u64 t, %1; cvt.u32.u64 %0, t; }" : "=r"(a) : "l"(p));
    return a;
}
__device__ __forceinline__ void ldm4(uint32_t* r, uint32_t addr) {
    asm volatile("ldmatrix.sync.aligned.m8n8.x4.shared.b16 {%0,%1,%2,%3}, [%4];"
                 : "=r"(r[0]), "=r"(r[1]), "=r"(r[2]), "=r"(r[3]) : "r"(addr));
}
__device__ __forceinline__ void mma16816h(float* c, const uint32_t* a, const uint32_t* b) {
    asm volatile("mma.sync.aligned.m16n8k16.row.col.f32.f16.f16.f32 "
                 "{%0,%1,%2,%3}, {%4,%5,%6,%7}, {%8,%9}, {%0,%1,%2,%3};"
                 : "+f"(c[0]), "+f"(c[1]), "+f"(c[2]), "+f"(c[3])
                 : "r"(a[0]), "r"(a[1]), "r"(a[2]), "r"(a[3]), "r"(b[0]), "r"(b[1]));
}
// named producer/consumer barriers (count = 256 = producers + consumers)
__device__ __forceinline__ void bar_sync(int id) {
    asm volatile("bar.sync %0, 256;" :: "r"(id) : "memory");
}
__device__ __forceinline__ void bar_arrive(int id) {
    asm volatile("bar.arrive %0, 256;" :: "r"(id) : "memory");
}
__device__ __forceinline__ uint32_t pkh(__half a, __half b) {
    __half2 t; t.x = a; t.y = b;
    return *reinterpret_cast<uint32_t*>(&t);
}

// ---------------- prep kernels ----------------
__global__ __launch_bounds__(256) void prep_x(const float* __restrict__ x) {
    size_t i = (size_t)blockIdx.x * 256 + threadIdx.x;  // float4 index
    const size_t total = (size_t)(NROWS + 1) * (HC / 4);
    if (i >= total) return;
    float4 v = make_float4(0.f, 0.f, 0.f, 0.f);
    if (i < (size_t)NROWS * (HC / 4)) v = reinterpret_cast<const float4*>(x)[i];
    reinterpret_cast<uint2*>(g_xf)[i] =
        make_uint2(pkh(__float2half(v.x), __float2half(v.y)),
                   pkh(__float2half(v.z), __float2half(v.w)));
}

// Fragment mapping (validated):
//   reg r element e of lane l = W[k][c][n],  c = ks*16 + (l&3)*2 + r*8 + e,
//   n = nt*8 + (l>>2).
__global__ __launch_bounds__(256) void prep_w(const float* __restrict__ Wa,
                                              const float* __restrict__ Wb) {
    int i = blockIdx.x * 256 + threadIdx.x;
    if (i >= 2 * WFRAG_PER_LAYER) return;
    const int L    = i / WFRAG_PER_LAYER;
    int rem        = i % WFRAG_PER_LAYER;
    const int k    = rem / 1024;  rem %= 1024;
    const int ks   = rem / 256;   rem %= 256;
    const int nt   = rem / 32;
    const int lane = rem % 32;
    const int n  = nt * 8 + (lane >> 2);
    const int c0 = ks * 16 + (lane & 3) * 2;
    const float* Wk = (L ? Wb : Wa) + (size_t)k * HC * HC;
    uint2 o;
    o.x = pkh(__float2half(Wk[(c0 + 0) * HC + n]),
              __float2half(Wk[(c0 + 1) * HC + n]));
    o.y = pkh(__float2half(Wk[(c0 + 8) * HC + n]),
              __float2half(Wk[(c0 + 9) * HC + n]));
    g_wf[i] = o;
}

// ---------------- main warp-specialized HMMA kernel ----------------
// Dynamic smem: nbr cache 13824B + 3 A stages x 16KB (XOR-swizzled 128B rows).
// Warps 0-3: consumers (MMA). Warps 4-7: producers (gather), run <=3 ahead.
#define NBR_BYTES (KOFF * TILE_M * 4)
#define STAGE_BYTES 16384
#define SMEM_TOTAL (NBR_BYTES + NSTAGE * STAGE_BYTES)

template <bool FIRST>
__global__ __launch_bounds__(256, 1)
void spconv_hmma(const __half* __restrict__ ff,
                 const uint2* __restrict__ wf,
                 const int* __restrict__ nbr,
                 const float* __restrict__ x,
                 __half* __restrict__ mf,
                 float* __restrict__ out)
{
    extern __shared__ __align__(128) char smx[];
    int* nbr_s = reinterpret_cast<int*>(smx);
    char* stages = smx + NBR_BYTES;
    const uint32_t sstage = smem_u32(stages);

    const int tid  = threadIdx.x;
    const int wid  = tid >> 5;
    const int lane = tid & 31;
    const int row0 = blockIdx.x * TILE_M;

    // ---- all 256 threads: fill nbr cache once ----
    for (int j = tid; j < KOFF * TILE_M; j += 256) {
        const int off = j / TILE_M, row = j % TILE_M;
        nbr_s[j] = nbr[(size_t)(row0 + row) * KOFF + off];
    }
    __syncthreads();

    if (wid >= 4) {
        // ================= producers: warps 4-7 =================
        const int ptid  = tid - 128;          // 0..127
        const int rsub  = ptid >> 3;          // 0..15
        const int chunk = ptid & 7;           // 16B chunk within 128B row
        for (int k = 0; k < KOFF; k++) {
            const int s = k % NSTAGE;
            if (k >= NSTAGE) bar_sync(4 + s);           // wait stage empty
            char* tg = stages + s * STAGE_BYTES;
            const int* nk = nbr_s + k * TILE_M;
            #pragma unroll
            for (int g = 0; g < 8; g++) {
                const int row = g * 16 + rsub;
                const int nb  = nk[row];
                const uint4 v = __ldg(reinterpret_cast<const uint4*>(
                                          ff + (size_t)nb * HC) + chunk);
                const uint32_t off = (uint32_t)row * 128 +
                                     (uint32_t)((chunk ^ (row & 7)) << 4);
                *reinterpret_cast<uint4*>(tg + off) = v;
            }
            bar_arrive(1 + s);                           // stage full
        }
        return;   // producers done; all consumer waits already funded
    }

    // ================= consumers: warps 0-3 =================
    // ldmatrix A lane decomposition (x4 = 4 8x8 b16 matrices)
    const int lm = lane & 7, lg = lane >> 3;
    const int a_row   = wid * 32 + (lg & 1) * 8 + lm;  // + t*16
    const int a_chunk = (lg >> 1);                     // + ks*2

    float acc[2][8][4];
    #pragma unroll
    for (int t = 0; t < 2; t++)
        #pragma unroll
        for (int n = 0; n < 8; n++)
            #pragma unroll
            for (int j = 0; j < 4; j++) acc[t][n][j] = 0.f;

    for (int k = 0; k < KOFF; k++) {
        const int s = k % NSTAGE;
        bar_sync(1 + s);                                 // wait stage full
        const uint32_t tb = sstage + (uint32_t)s * STAGE_BYTES;

        const uint2* wfk = wf + (size_t)k * (4 * 8 * 32);
        #pragma unroll
        for (int ks = 0; ks < 4; ks++) {
            uint32_t ah[2][4];
            #pragma unroll
            for (int t = 0; t < 2; t++) {
                const int rA = a_row + t * 16;
                const uint32_t cc = (uint32_t)(a_chunk + ks * 2);
                const uint32_t off = (uint32_t)rA * 128 + ((cc ^ (rA & 7)) << 4);
                ldm4(ah[t], tb + off);
            }
            #pragma unroll
            for (int nt = 0; nt < 8; nt++) {
                const uint2 bf = __ldg(&wfk[(ks * 8 + nt) * 32 + lane]);
                const uint32_t bb[2] = {bf.x, bf.y};
                #pragma unroll
                for (int t = 0; t < 2; t++)
                    mma16816h(acc[t][nt], ah[t], bb);
            }
        }
        bar_arrive(4 + s);                               // stage empty
    }

    // --- epilogue (register fragments -> global) ---
    const int erow = row0 + wid * 32 + (lane >> 2);
    const int ecol = (lane & 3) * 2;
    #pragma unroll
    for (int t = 0; t < 2; t++) {
        #pragma unroll
        for (int n = 0; n < 8; n++) {
            #pragma unroll
            for (int rr = 0; rr < 2; rr++) {
                const int r = erow + t * 16 + rr * 8;
                const int c = n * 8 + ecol;
                float v0 = acc[t][n][2 * rr];
                float v1 = acc[t][n][2 * rr + 1];
                if (FIRST) {
                    v0 = fmaxf(v0, 0.f);
                    v1 = fmaxf(v1, 0.f);
                    *reinterpret_cast<uint32_t*>(mf + (size_t)r * HC + c) =
                        pkh(__float2half(v0), __float2half(v1));
                } else {
                    const float2 xv =
                        *reinterpret_cast<const float2*>(x + (size_t)r * HC + c);
                    float2 o;
                    o.x = v0 + xv.x;
                    o.y = v1 + xv.y;
                    *reinterpret_cast<float2*>(out + (size_t)r * HC + c) = o;
                }
            }
        }
    }
}

// ---------------- launch ----------------
extern "C" void kernel_launch(void* const* d_in, const int* in_sizes, int n_in,
                              void* d_out, int out_size) {
    const float* x   = (const float*)d_in[0];
    const float* Wa  = (const float*)d_in[1];
    const float* Wb  = (const float*)d_in[2];
    const int*   nbr = (const int*)d_in[3];
    float*       out = (float*)d_out;

    __half *xf, *mf;
    uint2* wfp;
    cudaGetSymbolAddress((void**)&xf, g_xf);
    cudaGetSymbolAddress((void**)&mf, g_mf);
    cudaGetSymbolAddress((void**)&wfp, g_wf);

    cudaFuncSetAttribute(spconv_hmma<true>,
                         cudaFuncAttributeMaxDynamicSharedMemorySize, SMEM_TOTAL);
    cudaFuncSetAttribute(spconv_hmma<false>,
                         cudaFuncAttributeMaxDynamicSharedMemorySize, SMEM_TOTAL);

    const size_t xtot = (size_t)(NROWS + 1) * (HC / 4);
    prep_x<<<(int)((xtot + 255) / 256), 256>>>(x);
    prep_w<<<(2 * WFRAG_PER_LAYER + 255) / 256, 256>>>(Wa, Wb);

    // layer 1: relu(conv(x, Wa)) -> fp16 mid
    spconv_hmma<true><<<NBLK, 256, SMEM_TOTAL>>>(xf, wfp, nbr, nullptr, mf, nullptr);
    // layer 2: conv(mid, Wb) + x -> out
    spconv_hmma<false><<<NBLK, 256, SMEM_TOTAL>>>(mf, wfp + WFRAG_PER_LAYER, nbr, x,
                                                  nullptr, out);
}

// round 17
// speedup vs baseline: 1.7759x; 1.7759x over previous
#include <cuda_runtime.h>
#include <cuda_fp16.h>
#include <cstdint>

#define NROWS 262144
#define HC 64
#define KOFF 27
#define TILE_M 128
#define NBLK (NROWS / TILE_M)
#define NSTAGE 3
#define NTHREADS 384   // 8 consumer warps + 4 producer warps

// weight fragments per layer: 27 k * 4 ks * 8 nt * 32 lanes uint2 (fp16)
#define WFRAG_PER_LAYER (KOFF * 4 * 8 * 32)

// ---------------- device scratch (no allocations allowed) ----------------
// Row NROWS is a zero sentinel (zero-initialized, never written) so gathers
// need no bounds check.
__device__ __align__(128) __half g_xf[(size_t)(NROWS + 8) * HC];  // fp16 x
__device__ __align__(128) __half g_mf[(size_t)(NROWS + 8) * HC];  // fp16 mid
// W in mma-B fragment order: uint2 = {b_r0, b_r1}
__device__ uint2 g_wf[2 * WFRAG_PER_LAYER];

// ---------------- helpers (baseline PTX: ldmatrix / mma.sync / bar) ------
__device__ __forceinline__ uint32_t smem_u32(const void* p) {
    uint32_t a;
    asm("{ .reg .u64 t; cvta.to.shared.u64 t, %1; cvt.u32.u64 %0, t; }" : "=r"(a) : "l"(p));
    return a;
}
__device__ __forceinline__ void ldm4(uint32_t* r, uint32_t addr) {
    asm volatile("ldmatrix.sync.aligned.m8n8.x4.shared.b16 {%0,%1,%2,%3}, [%4];"
                 : "=r"(r[0]), "=r"(r[1]), "=r"(r[2]), "=r"(r[3]) : "r"(addr));
}
__device__ __forceinline__ void mma16816h(float* c, const uint32_t* a, const uint32_t* b) {
    asm volatile("mma.sync.aligned.m16n8k16.row.col.f32.f16.f16.f32 "
                 "{%0,%1,%2,%3}, {%4,%5,%6,%7}, {%8,%9}, {%0,%1,%2,%3};"
                 : "+f"(c[0]), "+f"(c[1]), "+f"(c[2]), "+f"(c[3])
                 : "r"(a[0]), "r"(a[1]), "r"(a[2]), "r"(a[3]), "r"(b[0]), "r"(b[1]));
}
// named producer/consumer barriers (count = 384 = 256 consumers + 128 producers)
__device__ __forceinline__ void bar_sync(int id) {
    asm volatile("bar.sync %0, 384;" :: "r"(id) : "memory");
}
__device__ __forceinline__ void bar_arrive(int id) {
    asm volatile("bar.arrive %0, 384;" :: "r"(id) : "memory");
}
__device__ __forceinline__ uint32_t pkh(__half a, __half b) {
    __half2 t; t.x = a; t.y = b;
    return *reinterpret_cast<uint32_t*>(&t);
}

// ---------------- prep kernels ----------------
__global__ __launch_bounds__(256) void prep_x(const float* __restrict__ x) {
    size_t i = (size_t)blockIdx.x * 256 + threadIdx.x;  // float4 index
    const size_t total = (size_t)(NROWS + 1) * (HC / 4);
    if (i >= total) return;
    float4 v = make_float4(0.f, 0.f, 0.f, 0.f);
    if (i < (size_t)NROWS * (HC / 4)) v = reinterpret_cast<const float4*>(x)[i];
    reinterpret_cast<uint2*>(g_xf)[i] =
        make_uint2(pkh(__float2half(v.x), __float2half(v.y)),
                   pkh(__float2half(v.z), __float2half(v.w)));
}

// Fragment mapping (validated):
//   reg r element e of lane l = W[k][c][n],  c = ks*16 + (l&3)*2 + r*8 + e,
//   n = nt*8 + (l>>2).
__global__ __launch_bounds__(256) void prep_w(const float* __restrict__ Wa,
                                              const float* __restrict__ Wb) {
    int i = blockIdx.x * 256 + threadIdx.x;
    if (i >= 2 * WFRAG_PER_LAYER) return;
    const int L    = i / WFRAG_PER_LAYER;
    int rem        = i % WFRAG_PER_LAYER;
    const int k    = rem / 1024;  rem %= 1024;
    const int ks   = rem / 256;   rem %= 256;
    const int nt   = rem / 32;
    const int lane = rem % 32;
    const int n  = nt * 8 + (lane >> 2);
    const int c0 = ks * 16 + (lane & 3) * 2;
    const float* Wk = (L ? Wb : Wa) + (size_t)k * HC * HC;
    uint2 o;
    o.x = pkh(__float2half(Wk[(c0 + 0) * HC + n]),
              __float2half(Wk[(c0 + 1) * HC + n]));
    o.y = pkh(__float2half(Wk[(c0 + 8) * HC + n]),
              __float2half(Wk[(c0 + 9) * HC + n]));
    g_wf[i] = o;
}

// ---------------- main warp-specialized HMMA kernel ----------------
// Dynamic smem: nbr cache 13824B + 3 A stages x 16KB (XOR-swizzled 128B rows).
// Warps 0-7: consumers (each m16 x n64). Warps 8-11: producers (gather).
#define NBR_BYTES (KOFF * TILE_M * 4)
#define STAGE_BYTES 16384
#define SMEM_TOTAL (NBR_BYTES + NSTAGE * STAGE_BYTES)

template <bool FIRST>
__global__ __launch_bounds__(NTHREADS, 2)
void spconv_hmma(const __half* __restrict__ ff,
                 const uint2* __restrict__ wf,
                 const int* __restrict__ nbr,
                 const float* __restrict__ x,
                 __half* __restrict__ mf,
                 float* __restrict__ out)
{
    extern __shared__ __align__(128) char smx[];
    int* nbr_s = reinterpret_cast<int*>(smx);
    char* stages = smx + NBR_BYTES;
    const uint32_t sstage = smem_u32(stages);

    const int tid  = threadIdx.x;
    const int wid  = tid >> 5;
    const int lane = tid & 31;
    const int row0 = blockIdx.x * TILE_M;

    // ---- all 384 threads: fill nbr cache once ----
    for (int j = tid; j < KOFF * TILE_M; j += NTHREADS) {
        const int off = j / TILE_M, row = j % TILE_M;
        nbr_s[j] = nbr[(size_t)(row0 + row) * KOFF + off];
    }
    __syncthreads();

    if (wid >= 8) {
        // ================= producers: warps 8-11 =================
        const int ptid  = tid - 256;          // 0..127
        const int rsub  = ptid >> 3;          // 0..15
        const int chunk = ptid & 7;           // 16B chunk within 128B row
        for (int k = 0; k < KOFF; k++) {
            const int s = k % NSTAGE;
            if (k >= NSTAGE) bar_sync(4 + s);           // wait stage empty
            char* tg = stages + s * STAGE_BYTES;
            const int* nk = nbr_s + k * TILE_M;
            #pragma unroll
            for (int g = 0; g < 8; g++) {
                const int row = g * 16 + rsub;
                const int nb  = nk[row];
                const uint4 v = __ldg(reinterpret_cast<const uint4*>(
                                          ff + (size_t)nb * HC) + chunk);
                const uint32_t off = (uint32_t)row * 128 +
                                     (uint32_t)((chunk ^ (row & 7)) << 4);
                *reinterpret_cast<uint4*>(tg + off) = v;
            }
            bar_arrive(1 + s);                           // stage full
        }
        return;   // producers done; all consumer waits already funded
    }

    // ================= consumers: warps 0-7 (m16 x n64 each) =============
    // ldmatrix A lane decomposition (x4 = 16x16 fp16 tile = 4 8x8 matrices)
    const int lm = lane & 7, lg = lane >> 3;
    const int a_row   = wid * 16 + (lg & 1) * 8 + lm;
    const int a_chunk = (lg >> 1);                     // + ks*2

    float acc[8][4];
    #pragma unroll
    for (int n = 0; n < 8; n++)
        #pragma unroll
        for (int j = 0; j < 4; j++) acc[n][j] = 0.f;

    for (int k = 0; k < KOFF; k++) {
        const int s = k % NSTAGE;
        bar_sync(1 + s);                                 // wait stage full
        const uint32_t tb = sstage + (uint32_t)s * STAGE_BYTES;

        const uint2* wfk = wf + (size_t)k * (4 * 8 * 32);
        #pragma unroll
        for (int ks = 0; ks < 4; ks++) {
            uint32_t ah[4];
            {
                const uint32_t cc = (uint32_t)(a_chunk + ks * 2);
                const uint32_t off = (uint32_t)a_row * 128 +
                                     ((cc ^ (a_row & 7)) << 4);
                ldm4(ah, tb + off);
            }
            #pragma unroll
            for (int nt = 0; nt < 8; nt++) {
                const uint2 bf = __ldg(&wfk[(ks * 8 + nt) * 32 + lane]);
                const uint32_t bb[2] = {bf.x, bf.y};
                mma16816h(acc[nt], ah, bb);
            }
        }
        bar_arrive(4 + s);                               // stage empty
    }

    // --- epilogue (register fragments -> global), m16 x n64 per warp ---
    const int erow = row0 + wid * 16 + (lane >> 2);
    const int ecol = (lane & 3) * 2;
    #pragma unroll
    for (int n = 0; n < 8; n++) {
        #pragma unroll
        for (int rr = 0; rr < 2; rr++) {
            const int r = erow + rr * 8;
            const int c = n * 8 + ecol;
            float v0 = acc[n][2 * rr];
            float v1 = acc[n][2 * rr + 1];
            if (FIRST) {
                v0 = fmaxf(v0, 0.f);
                v1 = fmaxf(v1, 0.f);
                *reinterpret_cast<uint32_t*>(mf + (size_t)r * HC + c) =
                    pkh(__float2half(v0), __float2half(v1));
            } else {
                const float2 xv =
                    *reinterpret_cast<const float2*>(x + (size_t)r * HC + c);
                float2 o;
                o.x = v0 + xv.x;
                o.y = v1 + xv.y;
                *reinterpret_cast<float2*>(out + (size_t)r * HC + c) = o;
            }
        }
    }
}

// ---------------- launch ----------------
extern "C" void kernel_launch(void* const* d_in, const int* in_sizes, int n_in,
                              void* d_out, int out_size) {
    const float* x   = (const float*)d_in[0];
    const float* Wa  = (const float*)d_in[1];
    const float* Wb  = (const float*)d_in[2];
    const int*   nbr = (const int*)d_in[3];
    float*       out = (float*)d_out;

    __half *xf, *mf;
    uint2* wfp;
    cudaGetSymbolAddress((void**)&xf, g_xf);
    cudaGetSymbolAddress((void**)&mf, g_mf);
    cudaGetSymbolAddress((void**)&wfp, g_wf);

    cudaFuncSetAttribute(spconv_hmma<true>,
                         cudaFuncAttributeMaxDynamicSharedMemorySize, SMEM_TOTAL);
    cudaFuncSetAttribute(spconv_hmma<false>,
                         cudaFuncAttributeMaxDynamicSharedMemorySize, SMEM_TOTAL);

    const size_t xtot = (size_t)(NROWS + 1) * (HC / 4);
    prep_x<<<(int)((xtot + 255) / 256), 256>>>(x);
    prep_w<<<(2 * WFRAG_PER_LAYER + 255) / 256, 256>>>(Wa, Wb);

    // layer 1: relu(conv(x, Wa)) -> fp16 mid
    spconv_hmma<true><<<NBLK, NTHREADS, SMEM_TOTAL>>>(
        xf, wfp, nbr, nullptr, mf, nullptr);
    // layer 2: conv(mid, Wb) + x -> out
    spconv_hmma<false><<<NBLK, NTHREADS, SMEM_TOTAL>>>(
        mf, wfp + WFRAG_PER_LAYER, nbr, x, nullptr, out);
}